// round 4
// baseline (speedup 1.0000x reference)
#include <cuda_runtime.h>
#include <math.h>

#define BTCH   2
#define SLEN   2048
#define HDIM   2304
#define NHQ    8
#define NKVH   4
#define HD     256
#define WIN    512
#define MTOK   4096      // B*S
#define QCOLS  2048      // NH*HD
#define KCOLS  1024      // NKV*HD

// ------------------------- scratch (device globals; no allocs allowed) ------
__device__ float g_q[MTOK * QCOLS];     // 33.5 MB
__device__ float g_k[MTOK * KCOLS];     // 16.8 MB
__device__ float g_v[MTOK * KCOLS];     // 16.8 MB
__device__ float g_attn[MTOK * QCOLS];  // 33.5 MB

typedef unsigned long long ull;

__device__ __forceinline__ ull pack_dup(float a) {
    ull r; asm("mov.b64 %0, {%1, %1};" : "=l"(r) : "f"(a)); return r;
}
__device__ __forceinline__ void fma2(ull& d, ull a, ull b) {
    asm("fma.rn.f32x2 %0, %1, %2, %0;" : "+l"(d) : "l"(a), "l"(b));
}
__device__ __forceinline__ void mul2(ull& d, ull a) {
    asm("mul.rn.f32x2 %0, %0, %1;" : "+l"(d) : "l"(a));
}
__device__ __forceinline__ void unpack2(ull v, float& lo, float& hi) {
    asm("mov.b64 {%0, %1}, %2;" : "=f"(lo), "=f"(hi) : "l"(v));
}

// ---------------------------------------------------------------------------
// fp32 GEMM: C[M,N] = A[M,K] @ B[K,N], row-major. 128x128x16 tiles, 256 thr,
// 8x8 microtile/thread, packed f32x2 FMA. M,N mult of 128; K mult of 16.
// amode: 0 -> A = Aarg, 1 -> A = g_attn
// cmode: 0 -> C = Carg, 1 -> g_q, 2 -> g_k, 3 -> g_v
// ---------------------------------------------------------------------------
__global__ void __launch_bounds__(256, 2) sgemm_kernel(
    const float* __restrict__ Aarg, const float* __restrict__ Bmat,
    float* __restrict__ Carg, int M, int N, int K, int amode, int cmode)
{
    __shared__ __align__(16) float As[16][132];  // A tile transposed [k][row]
    __shared__ __align__(16) float Bs[16][128];

    const float* A = (amode == 0) ? Aarg : (const float*)g_attn;
    float* C = (cmode == 0) ? Carg : (cmode == 1 ? g_q : (cmode == 2 ? g_k : g_v));

    const int tid  = threadIdx.x;
    const int tx   = tid & 15;
    const int ty   = tid >> 4;
    const int arow = tid >> 2;        // 0..63
    const int acol = (tid & 3) << 2;  // 0,4,8,12
    const int brow = tid >> 5;        // 0..7
    const int bcol = (tid & 31) << 2; // 0..124

    const float* Ab = A + (size_t)(blockIdx.y * 128) * K;
    const float* Bb = Bmat + blockIdx.x * 128;

    ull acc[8][4];
    #pragma unroll
    for (int i = 0; i < 8; i++)
        #pragma unroll
        for (int j = 0; j < 4; j++) acc[i][j] = 0ull;

    for (int k0 = 0; k0 < K; k0 += 16) {
        __syncthreads();
        #pragma unroll
        for (int r = 0; r < 2; r++) {
            float4 v = *(const float4*)(Ab + (size_t)(arow + (r << 6)) * K + k0 + acol);
            As[acol + 0][arow + (r << 6)] = v.x;
            As[acol + 1][arow + (r << 6)] = v.y;
            As[acol + 2][arow + (r << 6)] = v.z;
            As[acol + 3][arow + (r << 6)] = v.w;
            float4 w = *(const float4*)(Bb + (size_t)(k0 + brow + (r << 3)) * N + bcol);
            *(float4*)&Bs[brow + (r << 3)][bcol] = w;
        }
        __syncthreads();
        #pragma unroll
        for (int k = 0; k < 16; k++) {
            float4 a0 = *(const float4*)&As[k][ty << 3];
            float4 a1 = *(const float4*)&As[k][(ty << 3) + 4];
            const ull* b64 = (const ull*)&Bs[k][tx << 3];
            ull b0 = b64[0], b1 = b64[1], b2 = b64[2], b3 = b64[3];
            ull ad[8];
            ad[0] = pack_dup(a0.x); ad[1] = pack_dup(a0.y);
            ad[2] = pack_dup(a0.z); ad[3] = pack_dup(a0.w);
            ad[4] = pack_dup(a1.x); ad[5] = pack_dup(a1.y);
            ad[6] = pack_dup(a1.z); ad[7] = pack_dup(a1.w);
            #pragma unroll
            for (int i = 0; i < 8; i++) {
                fma2(acc[i][0], ad[i], b0);
                fma2(acc[i][1], ad[i], b1);
                fma2(acc[i][2], ad[i], b2);
                fma2(acc[i][3], ad[i], b3);
            }
        }
    }

    const int crow0 = blockIdx.y * 128 + (ty << 3);
    const int ccol0 = blockIdx.x * 128 + (tx << 3);
    #pragma unroll
    for (int i = 0; i < 8; i++) {
        float o[8];
        #pragma unroll
        for (int j = 0; j < 4; j++) unpack2(acc[i][j], o[2 * j], o[2 * j + 1]);
        float4* cp = (float4*)(C + (size_t)(crow0 + i) * N + ccol0);
        cp[0] = make_float4(o[0], o[1], o[2], o[3]);
        cp[1] = make_float4(o[4], o[5], o[6], o[7]);
    }
}

// ---------------------------------------------------------------------------
// RoPE in-place on g_q (8 heads) and g_k (4 heads).
// one thread per (token, head, d-pair), d in [0,128)
// ---------------------------------------------------------------------------
__global__ void rope_kernel(const int* __restrict__ pos_ids)
{
    int idx = blockIdx.x * blockDim.x + threadIdx.x;
    if (idx >= MTOK * 12 * 128) return;
    int d  = idx & 127;
    int r  = idx >> 7;
    int hh = r % 12;             // 0..7 -> Q heads, 8..11 -> K heads
    int t  = r / 12;             // token 0..4095
    float pos = (float)pos_ids[t];
    // inv_freq = 10000^{-d/128} = exp(-d * ln(10000)/128)
    float inv = __expf((float)d * -0.07195578415606394f);
    float ang = pos * inv;
    float sn, cs;
    sincosf(ang, &sn, &cs);
    float* base = (hh < 8) ? (g_q + (size_t)t * QCOLS + hh * HD)
                           : (g_k + (size_t)t * KCOLS + (hh - 8) * HD);
    float x1 = base[d];
    float x2 = base[d + 128];
    base[d]       = x1 * cs - x2 * sn;
    base[d + 128] = x2 * cs + x1 * sn;
}

// ---------------------------------------------------------------------------
// Sliding-window causal flash attention with tanh softcap.
// grid (S/64, NH, B), 256 threads. 64 queries x 64-key blocks, online softmax.
// Thread (tx,ty): scores 4q x 4k; output 4q x 16d (d = 64j + tx*4, j<4).
// ---------------------------------------------------------------------------
__global__ void __launch_bounds__(256, 2) attn_kernel()
{
    __shared__ __align__(16) float sQ[16][68];    // [d][query]
    __shared__ __align__(16) float sK[16][68];    // [d][key]
    __shared__ __align__(16) float sP[64][69];    // [key][query]
    __shared__ __align__(16) float sV[16][264];   // [key][d]

    const int qt = blockIdx.x, h = blockIdx.y, b = blockIdx.z;
    const int kvh = h >> 1;
    const int q0 = qt * 64;
    const int tid = threadIdx.x;
    const int tx = tid & 15, ty = tid >> 4;

    const float* Qg = g_q + ((size_t)(b * SLEN + q0)) * QCOLS + h * HD;
    const float* Kg = g_k + ((size_t)(b * SLEN)) * KCOLS + kvh * HD;
    const float* Vg = g_v + ((size_t)(b * SLEN)) * KCOLS + kvh * HD;

    ull acc[4][8];
    #pragma unroll
    for (int i = 0; i < 4; i++)
        #pragma unroll
        for (int j = 0; j < 8; j++) acc[i][j] = 0ull;
    float mrow[4] = {-1e30f, -1e30f, -1e30f, -1e30f};
    float lrow[4] = {0.f, 0.f, 0.f, 0.f};

    const int ld_d = tid & 15;       // d within chunk
    const int ld_q = tid >> 4;       // base row (0..15)

    const int kb_start = (qt >= 8) ? (qt - 8) : 0;
    for (int kb = kb_start; kb <= qt; kb++) {
        // ---- scores: S = Q K^T over d-chunks of 16 ----
        ull s[4][2];
        #pragma unroll
        for (int i = 0; i < 4; i++) { s[i][0] = 0ull; s[i][1] = 0ull; }

        for (int dc = 0; dc < HD; dc += 16) {
            __syncthreads();
            #pragma unroll
            for (int r = 0; r < 4; r++) {
                int row = ld_q + 16 * r;
                sQ[ld_d][row] = Qg[(size_t)row * QCOLS + dc + ld_d];
                sK[ld_d][row] = Kg[(size_t)(kb * 64 + row) * KCOLS + dc + ld_d];
            }
            __syncthreads();
            #pragma unroll
            for (int d = 0; d < 16; d++) {
                const ull* kp = (const ull*)&sK[d][tx << 2];
                ull b0 = kp[0], b1 = kp[1];
                #pragma unroll
                for (int i = 0; i < 4; i++) {
                    ull ad = pack_dup(sQ[d][(ty << 2) + i]);
                    fma2(s[i][0], ad, b0);
                    fma2(s[i][1], ad, b1);
                }
            }
        }

        // ---- softcap + mask + online softmax ----
        float sc[4][4];
        const int ig0 = q0 + (ty << 2);
        const int jg0 = kb * 64 + (tx << 2);
        #pragma unroll
        for (int i = 0; i < 4; i++) {
            float v0, v1, v2, v3;
            unpack2(s[i][0], v0, v1);
            unpack2(s[i][1], v2, v3);
            float vv[4] = {v0, v1, v2, v3};
            int ig = ig0 + i;
            #pragma unroll
            for (int j = 0; j < 4; j++) {
                int jg = jg0 + j;
                float x = vv[j] * 0.0625f;            // /sqrt(256)
                float t = __expf(x * 0.04f);          // e^{2x/50}
                float c = 50.f * (t - 1.f) / (t + 1.f);
                bool valid = (jg <= ig) && (ig - jg < WIN);
                sc[i][j] = valid ? c : -1e30f;
            }
        }
        #pragma unroll
        for (int i = 0; i < 4; i++) {
            float rmax = fmaxf(fmaxf(sc[i][0], sc[i][1]), fmaxf(sc[i][2], sc[i][3]));
            #pragma unroll
            for (int mseg = 1; mseg < 16; mseg <<= 1)
                rmax = fmaxf(rmax, __shfl_xor_sync(0xffffffffu, rmax, mseg));
            float mnew = fmaxf(mrow[i], rmax);
            float alpha = __expf(mrow[i] - mnew);
            float rsum = 0.f;
            #pragma unroll
            for (int j = 0; j < 4; j++) {
                float p = (sc[i][j] < -1e29f) ? 0.f : __expf(sc[i][j] - mnew);
                sc[i][j] = p;
                rsum += p;
            }
            #pragma unroll
            for (int mseg = 1; mseg < 16; mseg <<= 1)
                rsum += __shfl_xor_sync(0xffffffffu, rsum, mseg);
            lrow[i] = lrow[i] * alpha + rsum;
            mrow[i] = mnew;
            ull ad = pack_dup(alpha);
            #pragma unroll
            for (int j2 = 0; j2 < 8; j2++) mul2(acc[i][j2], ad);
        }
        #pragma unroll
        for (int i = 0; i < 4; i++)
            #pragma unroll
            for (int j = 0; j < 4; j++)
                sP[(tx << 2) + j][(ty << 2) + i] = sc[i][j];

        // ---- PV: O += P V over key-chunks of 16 ----
        const int vkk = tid >> 6;          // 0..3
        const int vc4 = (tid & 63) << 2;   // d base 0..252
        for (int kc = 0; kc < 4; kc++) {
            __syncthreads();
            const float* vb = Vg + (size_t)(kb * 64 + kc * 16) * KCOLS;
            #pragma unroll
            for (int r = 0; r < 4; r++) {
                float4 vv = *(const float4*)(vb + (size_t)(vkk + 4 * r) * KCOLS + vc4);
                *(float4*)&sV[vkk + 4 * r][vc4] = vv;
            }
            __syncthreads();
            #pragma unroll
            for (int k = 0; k < 16; k++) {
                ull vreg[8];
                #pragma unroll
                for (int j = 0; j < 4; j++) {
                    const ull* vp = (const ull*)&sV[k][(j << 6) + (tx << 2)];
                    vreg[2 * j] = vp[0];
                    vreg[2 * j + 1] = vp[1];
                }
                #pragma unroll
                for (int i = 0; i < 4; i++) {
                    ull pd = pack_dup(sP[kc * 16 + k][(ty << 2) + i]);
                    #pragma unroll
                    for (int j2 = 0; j2 < 8; j2++) fma2(acc[i][j2], pd, vreg[j2]);
                }
            }
        }
    }

    // ---- epilogue: O / l -> g_attn[token][h*256 + d] ----
    const int t0 = b * SLEN + q0;
    #pragma unroll
    for (int i = 0; i < 4; i++) {
        float rl = 1.f / lrow[i];
        float* ob = g_attn + (size_t)(t0 + (ty << 2) + i) * QCOLS + h * HD;
        #pragma unroll
        for (int j = 0; j < 4; j++) {
            float o0, o1, o2, o3;
            unpack2(acc[i][2 * j],     o0, o1);
            unpack2(acc[i][2 * j + 1], o2, o3);
            *(float4*)(ob + (j << 6) + (tx << 2)) =
                make_float4(o0 * rl, o1 * rl, o2 * rl, o3 * rl);
        }
    }
}

// ---------------------------------------------------------------------------
extern "C" void kernel_launch(void* const* d_in, const int* in_sizes, int n_in,
                              void* d_out, int out_size) {
    const float* hidden = (const float*)d_in[0];
    // d_in[1] = attention_mask (unused: mask computed analytically)
    const int*   pos    = (const int*)d_in[2];
    const float* Wq     = (const float*)d_in[3];
    const float* Wk     = (const float*)d_in[4];
    const float* Wv     = (const float*)d_in[5];
    const float* Wo     = (const float*)d_in[6];
    float* out = (float*)d_out;

    dim3 thr(256);
    // QKV projections
    sgemm_kernel<<<dim3(QCOLS / 128, MTOK / 128), thr>>>(
        hidden, Wq, nullptr, MTOK, QCOLS, HDIM, 0, 1);
    sgemm_kernel<<<dim3(KCOLS / 128, MTOK / 128), thr>>>(
        hidden, Wk, nullptr, MTOK, KCOLS, HDIM, 0, 2);
    sgemm_kernel<<<dim3(KCOLS / 128, MTOK / 128), thr>>>(
        hidden, Wv, nullptr, MTOK, KCOLS, HDIM, 0, 3);
    // RoPE on Q and K
    int rope_threads = MTOK * 12 * 128;
    rope_kernel<<<(rope_threads + 255) / 256, thr>>>(pos);
    // attention
    attn_kernel<<<dim3(SLEN / 64, NHQ, BTCH), thr>>>();
    // output projection
    sgemm_kernel<<<dim3(HDIM / 128, MTOK / 128), thr>>>(
        nullptr, Wo, out, MTOK, HDIM, QCOLS, 1, 0);
}

// round 5
// speedup vs baseline: 1.0009x; 1.0009x over previous
#include <cuda_runtime.h>
#include <cuda_bf16.h>
#include <math.h>
#include <stdint.h>

#define BTCH   2
#define SLEN   2048
#define HDIM   2304
#define NHQ    8
#define NKVH   4
#define HD     256
#define WIN    512
#define MTOK   4096      // B*S
#define QCOLS  2048      // NH*HD
#define KCOLS  1024      // NKV*HD

// ------------------------- scratch (device globals; no allocs allowed) ------
__device__ float g_q[MTOK * QCOLS];     // 33.5 MB
__device__ float g_k[MTOK * KCOLS];     // 16.8 MB
__device__ float g_v[MTOK * KCOLS];     // 16.8 MB
__device__ float g_attn[MTOK * QCOLS];  // 33.5 MB

typedef unsigned long long ull;

__device__ __forceinline__ ull pack_dup(float a) {
    ull r; asm("mov.b64 %0, {%1, %1};" : "=l"(r) : "f"(a)); return r;
}
__device__ __forceinline__ void fma2(ull& d, ull a, ull b) {
    asm("fma.rn.f32x2 %0, %1, %2, %0;" : "+l"(d) : "l"(a), "l"(b));
}
__device__ __forceinline__ void mul2(ull& d, ull a) {
    asm("mul.rn.f32x2 %0, %0, %1;" : "+l"(d) : "l"(a));
}
__device__ __forceinline__ void unpack2(ull v, float& lo, float& hi) {
    asm("mov.b64 {%0, %1}, %2;" : "=f"(lo), "=f"(hi) : "l"(v));
}

// ------------------------- tensor-core helpers -----------------------------
__device__ __forceinline__ uint32_t sptr(const void* p) {
    return (uint32_t)__cvta_generic_to_shared(p);
}
__device__ __forceinline__ void ldsm_x4(uint32_t* r, uint32_t a) {
    asm volatile("ldmatrix.sync.aligned.m8n8.x4.shared.b16 {%0,%1,%2,%3}, [%4];"
        : "=r"(r[0]), "=r"(r[1]), "=r"(r[2]), "=r"(r[3]) : "r"(a));
}
__device__ __forceinline__ void ldsm_x2(uint32_t* r, uint32_t a) {
    asm volatile("ldmatrix.sync.aligned.m8n8.x2.shared.b16 {%0,%1}, [%2];"
        : "=r"(r[0]), "=r"(r[1]) : "r"(a));
}
__device__ __forceinline__ void mma_bf16(float* c, const uint32_t* a, const uint32_t* b) {
    asm volatile("mma.sync.aligned.m16n8k16.row.col.f32.bf16.bf16.f32 "
        "{%0,%1,%2,%3}, {%4,%5,%6,%7}, {%8,%9}, {%0,%1,%2,%3};"
        : "+f"(c[0]), "+f"(c[1]), "+f"(c[2]), "+f"(c[3])
        : "r"(a[0]), "r"(a[1]), "r"(a[2]), "r"(a[3]), "r"(b[0]), "r"(b[1]));
}
__device__ __forceinline__ void split_bf16(float v, __nv_bfloat16& h, __nv_bfloat16& l) {
    h = __float2bfloat16(v);
    l = __float2bfloat16(v - __bfloat162float(h));
}

// ---------------------------------------------------------------------------
// Split-bf16 tensor-core GEMM: C[M,N] = A[M,K] @ B[K,N], fp32 in/out.
// Each fp32 operand split into hi+lo bf16; C = Ah*Bh + Ah*Bl + Al*Bh with
// fp32 accumulate (error ~2^-18). 128x128x16 tiles, 256 threads, 8 warps
// (2x4), warp tile 64x32, mma.sync m16n8k16 via ldmatrix fragments.
// M,N multiples of 128; K multiple of 16.
// amode: 0 -> A = Aarg, 1 -> A = g_attn
// cmode: 0 -> C = Carg, 1 -> g_q, 2 -> g_k, 3 -> g_v
// ---------------------------------------------------------------------------
__global__ void __launch_bounds__(256, 2) hgemm_split_kernel(
    const float* __restrict__ Aarg, const float* __restrict__ Bmat,
    float* __restrict__ Carg, int M, int N, int K, int amode, int cmode)
{
    __shared__ __align__(16) __nv_bfloat16 sAh[128][24];  // [m][k], pad->24
    __shared__ __align__(16) __nv_bfloat16 sAl[128][24];
    __shared__ __align__(16) __nv_bfloat16 sBh[128][24];  // [n][k]
    __shared__ __align__(16) __nv_bfloat16 sBl[128][24];

    const float* A = (amode == 0) ? Aarg : (const float*)g_attn;
    float* C = (cmode == 0) ? Carg : (cmode == 1 ? g_q : (cmode == 2 ? g_k : g_v));

    const int tid  = threadIdx.x;
    const int lane = tid & 31;
    const int warp = tid >> 5;
    const int wm = warp >> 2;          // 0..1
    const int wn = warp & 3;           // 0..3
    const int bm = blockIdx.y * 128;
    const int bn = blockIdx.x * 128;

    // A loader: rows tid>>2 (+64), 4 cols (tid&3)*4
    const int a_row0 = tid >> 2;
    const int a_c4   = (tid & 3) << 2;

    float c[4][4][4];
    #pragma unroll
    for (int mt = 0; mt < 4; mt++)
        #pragma unroll
        for (int nt = 0; nt < 4; nt++)
            #pragma unroll
            for (int i = 0; i < 4; i++) c[mt][nt][i] = 0.f;

    const float* Ab = A + (size_t)bm * K;
    const float* Bb = Bmat + bn;

    // prefetch k0 = 0
    float4 pa[2], pb[2];
    #pragma unroll
    for (int r = 0; r < 2; r++) {
        pa[r] = *(const float4*)(Ab + (size_t)(a_row0 + r * 64) * K + a_c4);
        int idx = tid + r * 256;
        int kk = idx >> 5, n4 = (idx & 31) << 2;
        pb[r] = *(const float4*)(Bb + (size_t)kk * N + n4);
    }

    for (int k0 = 0; k0 < K; k0 += 16) {
        // ---- stage prefetched fp32 into hi/lo bf16 smem tiles ----
        #pragma unroll
        for (int r = 0; r < 2; r++) {
            int row = a_row0 + r * 64;
            float av[4] = {pa[r].x, pa[r].y, pa[r].z, pa[r].w};
            #pragma unroll
            for (int j = 0; j < 4; j++) {
                __nv_bfloat16 h, l;
                split_bf16(av[j], h, l);
                sAh[row][a_c4 + j] = h;
                sAl[row][a_c4 + j] = l;
            }
            int idx = tid + r * 256;
            int kk = idx >> 5, n4 = (idx & 31) << 2;
            float bv[4] = {pb[r].x, pb[r].y, pb[r].z, pb[r].w};
            #pragma unroll
            for (int j = 0; j < 4; j++) {
                __nv_bfloat16 h, l;
                split_bf16(bv[j], h, l);
                sBh[n4 + j][kk] = h;    // transposed: [n][k]
                sBl[n4 + j][kk] = l;
            }
        }
        __syncthreads();

        // ---- prefetch next k-chunk (overlaps with mma below) ----
        if (k0 + 16 < K) {
            #pragma unroll
            for (int r = 0; r < 2; r++) {
                pa[r] = *(const float4*)(Ab + (size_t)(a_row0 + r * 64) * K + (k0 + 16) + a_c4);
                int idx = tid + r * 256;
                int kk = idx >> 5, n4 = (idx & 31) << 2;
                pb[r] = *(const float4*)(Bb + (size_t)(k0 + 16 + kk) * N + n4);
            }
        }

        // ---- fragments + mma ----
        uint32_t bh[4][2], bl[4][2];
        const int b_r = lane & 7;
        const int b_c = ((lane >> 3) & 1) << 3;
        #pragma unroll
        for (int nt = 0; nt < 4; nt++) {
            ldsm_x2(bh[nt], sptr(&sBh[wn * 32 + nt * 8 + b_r][b_c]));
            ldsm_x2(bl[nt], sptr(&sBl[wn * 32 + nt * 8 + b_r][b_c]));
        }
        const int a_r = (lane & 7) | (((lane >> 3) & 1) << 3);
        const int a_c = ((lane >> 4) & 1) << 3;
        #pragma unroll
        for (int mt = 0; mt < 4; mt++) {
            uint32_t ah[4], al[4];
            ldsm_x4(ah, sptr(&sAh[wm * 64 + mt * 16 + a_r][a_c]));
            ldsm_x4(al, sptr(&sAl[wm * 64 + mt * 16 + a_r][a_c]));
            #pragma unroll
            for (int nt = 0; nt < 4; nt++) {
                mma_bf16(c[mt][nt], ah, bh[nt]);   // hi*hi
                mma_bf16(c[mt][nt], ah, bl[nt]);   // hi*lo
                mma_bf16(c[mt][nt], al, bh[nt]);   // lo*hi
            }
        }
        __syncthreads();
    }

    // ---- epilogue ----
    #pragma unroll
    for (int mt = 0; mt < 4; mt++) {
        int row = bm + wm * 64 + mt * 16 + (lane >> 2);
        #pragma unroll
        for (int nt = 0; nt < 4; nt++) {
            int col = bn + wn * 32 + nt * 8 + ((lane & 3) << 1);
            float2 v01 = make_float2(c[mt][nt][0], c[mt][nt][1]);
            float2 v23 = make_float2(c[mt][nt][2], c[mt][nt][3]);
            *(float2*)(C + (size_t)row * N + col)       = v01;
            *(float2*)(C + (size_t)(row + 8) * N + col) = v23;
        }
    }
}

// ---------------------------------------------------------------------------
// RoPE in-place on g_q (8 heads) and g_k (4 heads).
// one thread per (token, head, d-pair), d in [0,128)
// ---------------------------------------------------------------------------
__global__ void rope_kernel(const int* __restrict__ pos_ids)
{
    int idx = blockIdx.x * blockDim.x + threadIdx.x;
    if (idx >= MTOK * 12 * 128) return;
    int d  = idx & 127;
    int r  = idx >> 7;
    int hh = r % 12;             // 0..7 -> Q heads, 8..11 -> K heads
    int t  = r / 12;             // token 0..4095
    float pos = (float)pos_ids[t];
    float inv = __expf((float)d * -0.07195578415606394f);  // 10000^{-d/128}
    float ang = pos * inv;
    float sn, cs;
    sincosf(ang, &sn, &cs);
    float* base = (hh < 8) ? (g_q + (size_t)t * QCOLS + hh * HD)
                           : (g_k + (size_t)t * KCOLS + (hh - 8) * HD);
    float x1 = base[d];
    float x2 = base[d + 128];
    base[d]       = x1 * cs - x2 * sn;
    base[d + 128] = x2 * cs + x1 * sn;
}

// ---------------------------------------------------------------------------
// Sliding-window causal flash attention with tanh softcap.
// grid (S/64, NH, B), 256 threads. 64 queries x 64-key blocks, online softmax.
// ---------------------------------------------------------------------------
__global__ void __launch_bounds__(256, 2) attn_kernel()
{
    __shared__ __align__(16) float sQ[16][68];    // [d][query]
    __shared__ __align__(16) float sK[16][68];    // [d][key]
    __shared__ __align__(16) float sP[64][69];    // [key][query]
    __shared__ __align__(16) float sV[16][264];   // [key][d]

    const int qt = blockIdx.x, h = blockIdx.y, b = blockIdx.z;
    const int kvh = h >> 1;
    const int q0 = qt * 64;
    const int tid = threadIdx.x;
    const int tx = tid & 15, ty = tid >> 4;

    const float* Qg = g_q + ((size_t)(b * SLEN + q0)) * QCOLS + h * HD;
    const float* Kg = g_k + ((size_t)(b * SLEN)) * KCOLS + kvh * HD;
    const float* Vg = g_v + ((size_t)(b * SLEN)) * KCOLS + kvh * HD;

    ull acc[4][8];
    #pragma unroll
    for (int i = 0; i < 4; i++)
        #pragma unroll
        for (int j = 0; j < 8; j++) acc[i][j] = 0ull;
    float mrow[4] = {-1e30f, -1e30f, -1e30f, -1e30f};
    float lrow[4] = {0.f, 0.f, 0.f, 0.f};

    const int ld_d = tid & 15;
    const int ld_q = tid >> 4;

    const int kb_start = (qt >= 8) ? (qt - 8) : 0;
    for (int kb = kb_start; kb <= qt; kb++) {
        // ---- scores: S = Q K^T over d-chunks of 16 ----
        ull s[4][2];
        #pragma unroll
        for (int i = 0; i < 4; i++) { s[i][0] = 0ull; s[i][1] = 0ull; }

        for (int dc = 0; dc < HD; dc += 16) {
            __syncthreads();
            #pragma unroll
            for (int r = 0; r < 4; r++) {
                int row = ld_q + 16 * r;
                sQ[ld_d][row] = Qg[(size_t)row * QCOLS + dc + ld_d];
                sK[ld_d][row] = Kg[(size_t)(kb * 64 + row) * KCOLS + dc + ld_d];
            }
            __syncthreads();
            #pragma unroll
            for (int d = 0; d < 16; d++) {
                const ull* kp = (const ull*)&sK[d][tx << 2];
                ull b0 = kp[0], b1 = kp[1];
                #pragma unroll
                for (int i = 0; i < 4; i++) {
                    ull ad = pack_dup(sQ[d][(ty << 2) + i]);
                    fma2(s[i][0], ad, b0);
                    fma2(s[i][1], ad, b1);
                }
            }
        }

        // ---- softcap + mask + online softmax ----
        float sc[4][4];
        const int ig0 = q0 + (ty << 2);
        const int jg0 = kb * 64 + (tx << 2);
        #pragma unroll
        for (int i = 0; i < 4; i++) {
            float v0, v1, v2, v3;
            unpack2(s[i][0], v0, v1);
            unpack2(s[i][1], v2, v3);
            float vv[4] = {v0, v1, v2, v3};
            int ig = ig0 + i;
            #pragma unroll
            for (int j = 0; j < 4; j++) {
                int jg = jg0 + j;
                float x = vv[j] * 0.0625f;            // /sqrt(256)
                float t = __expf(x * 0.04f);          // e^{2x/50}
                float cc = 50.f * (t - 1.f) / (t + 1.f);
                bool valid = (jg <= ig) && (ig - jg < WIN);
                sc[i][j] = valid ? cc : -1e30f;
            }
        }
        #pragma unroll
        for (int i = 0; i < 4; i++) {
            float rmax = fmaxf(fmaxf(sc[i][0], sc[i][1]), fmaxf(sc[i][2], sc[i][3]));
            #pragma unroll
            for (int mseg = 1; mseg < 16; mseg <<= 1)
                rmax = fmaxf(rmax, __shfl_xor_sync(0xffffffffu, rmax, mseg));
            float mnew = fmaxf(mrow[i], rmax);
            float alpha = __expf(mrow[i] - mnew);
            float rsum = 0.f;
            #pragma unroll
            for (int j = 0; j < 4; j++) {
                float p = (sc[i][j] < -1e29f) ? 0.f : __expf(sc[i][j] - mnew);
                sc[i][j] = p;
                rsum += p;
            }
            #pragma unroll
            for (int mseg = 1; mseg < 16; mseg <<= 1)
                rsum += __shfl_xor_sync(0xffffffffu, rsum, mseg);
            lrow[i] = lrow[i] * alpha + rsum;
            mrow[i] = mnew;
            ull ad = pack_dup(alpha);
            #pragma unroll
            for (int j2 = 0; j2 < 8; j2++) mul2(acc[i][j2], ad);
        }
        #pragma unroll
        for (int i = 0; i < 4; i++)
            #pragma unroll
            for (int j = 0; j < 4; j++)
                sP[(tx << 2) + j][(ty << 2) + i] = sc[i][j];

        // ---- PV: O += P V over key-chunks of 16 ----
        const int vkk = tid >> 6;
        const int vc4 = (tid & 63) << 2;
        for (int kc = 0; kc < 4; kc++) {
            __syncthreads();
            const float* vb = Vg + (size_t)(kb * 64 + kc * 16) * KCOLS;
            #pragma unroll
            for (int r = 0; r < 4; r++) {
                float4 vv = *(const float4*)(vb + (size_t)(vkk + 4 * r) * KCOLS + vc4);
                *(float4*)&sV[vkk + 4 * r][vc4] = vv;
            }
            __syncthreads();
            #pragma unroll
            for (int k = 0; k < 16; k++) {
                ull vreg[8];
                #pragma unroll
                for (int j = 0; j < 4; j++) {
                    const ull* vp = (const ull*)&sV[k][(j << 6) + (tx << 2)];
                    vreg[2 * j] = vp[0];
                    vreg[2 * j + 1] = vp[1];
                }
                #pragma unroll
                for (int i = 0; i < 4; i++) {
                    ull pd = pack_dup(sP[kc * 16 + k][(ty << 2) + i]);
                    #pragma unroll
                    for (int j2 = 0; j2 < 8; j2++) fma2(acc[i][j2], pd, vreg[j2]);
                }
            }
        }
    }

    // ---- epilogue: O / l -> g_attn[token][h*256 + d] ----
    const int t0 = b * SLEN + q0;
    #pragma unroll
    for (int i = 0; i < 4; i++) {
        float rl = 1.f / lrow[i];
        float* ob = g_attn + (size_t)(t0 + (ty << 2) + i) * QCOLS + h * HD;
        #pragma unroll
        for (int j = 0; j < 4; j++) {
            float o0, o1, o2, o3;
            unpack2(acc[i][2 * j],     o0, o1);
            unpack2(acc[i][2 * j + 1], o2, o3);
            *(float4*)(ob + (j << 6) + (tx << 2)) =
                make_float4(o0 * rl, o1 * rl, o2 * rl, o3 * rl);
        }
    }
}

// ---------------------------------------------------------------------------
extern "C" void kernel_launch(void* const* d_in, const int* in_sizes, int n_in,
                              void* d_out, int out_size) {
    const float* hidden = (const float*)d_in[0];
    // d_in[1] = attention_mask (unused: mask computed analytically)
    const int*   pos    = (const int*)d_in[2];
    const float* Wq     = (const float*)d_in[3];
    const float* Wk     = (const float*)d_in[4];
    const float* Wv     = (const float*)d_in[5];
    const float* Wo     = (const float*)d_in[6];
    float* out = (float*)d_out;

    dim3 thr(256);
    // QKV projections (split-bf16 tensor cores)
    hgemm_split_kernel<<<dim3(QCOLS / 128, MTOK / 128), thr>>>(
        hidden, Wq, nullptr, MTOK, QCOLS, HDIM, 0, 1);
    hgemm_split_kernel<<<dim3(KCOLS / 128, MTOK / 128), thr>>>(
        hidden, Wk, nullptr, MTOK, KCOLS, HDIM, 0, 2);
    hgemm_split_kernel<<<dim3(KCOLS / 128, MTOK / 128), thr>>>(
        hidden, Wv, nullptr, MTOK, KCOLS, HDIM, 0, 3);
    // RoPE on Q and K
    int rope_threads = MTOK * 12 * 128;
    rope_kernel<<<(rope_threads + 255) / 256, thr>>>(pos);
    // attention
    attn_kernel<<<dim3(SLEN / 64, NHQ, BTCH), thr>>>();
    // output projection
    hgemm_split_kernel<<<dim3(HDIM / 128, MTOK / 128), thr>>>(
        nullptr, Wo, out, MTOK, HDIM, QCOLS, 1, 0);
}

// round 7
// speedup vs baseline: 1.9125x; 1.9108x over previous
#include <cuda_runtime.h>
#include <cuda_bf16.h>
#include <math.h>
#include <stdint.h>

#define BTCH   2
#define SLEN   2048
#define HDIM   2304
#define NHQ    8
#define NKVH   4
#define HD     256
#define WIN    512
#define MTOK   4096      // B*S
#define QCOLS  2048      // NH*HD
#define KCOLS  1024      // NKV*HD

// ------------------------- scratch (device globals; no allocs allowed) ------
__device__ float g_q[MTOK * QCOLS];
__device__ float g_k[MTOK * KCOLS];
__device__ float g_v[MTOK * KCOLS];
__device__ float g_attn[MTOK * QCOLS];

// pre-split bf16 operands
__device__ __align__(16) __nv_bfloat16 g_hidH[MTOK * HDIM], g_hidL[MTOK * HDIM];
__device__ __align__(16) __nv_bfloat16 g_wqH[QCOLS * HDIM], g_wqL[QCOLS * HDIM];
__device__ __align__(16) __nv_bfloat16 g_wkH[KCOLS * HDIM], g_wkL[KCOLS * HDIM];
__device__ __align__(16) __nv_bfloat16 g_wvH[KCOLS * HDIM], g_wvL[KCOLS * HDIM];
__device__ __align__(16) __nv_bfloat16 g_woH[HDIM * QCOLS], g_woL[HDIM * QCOLS];
__device__ __align__(16) __nv_bfloat16 g_aoH[MTOK * QCOLS], g_aoL[MTOK * QCOLS];

typedef unsigned long long ull;

// ------------------------- f32x2 helpers (attention) -----------------------
__device__ __forceinline__ ull pack_dup(float a) {
    ull r; asm("mov.b64 %0, {%1, %1};" : "=l"(r) : "f"(a)); return r;
}
__device__ __forceinline__ void fma2(ull& d, ull a, ull b) {
    asm("fma.rn.f32x2 %0, %1, %2, %0;" : "+l"(d) : "l"(a), "l"(b));
}
__device__ __forceinline__ void mul2(ull& d, ull a) {
    asm("mul.rn.f32x2 %0, %0, %1;" : "+l"(d) : "l"(a));
}
__device__ __forceinline__ void unpack2(ull v, float& lo, float& hi) {
    asm("mov.b64 {%0, %1}, %2;" : "=f"(lo), "=f"(hi) : "l"(v));
}

// ------------------------- tensor-core (mma.sync) helpers ------------------
__device__ __forceinline__ uint32_t sptr(const void* p) {
    return (uint32_t)__cvta_generic_to_shared(p);
}
__device__ __forceinline__ void ldsm_x4(uint32_t* r, uint32_t a) {
    asm volatile("ldmatrix.sync.aligned.m8n8.x4.shared.b16 {%0,%1,%2,%3}, [%4];"
        : "=r"(r[0]), "=r"(r[1]), "=r"(r[2]), "=r"(r[3]) : "r"(a));
}
__device__ __forceinline__ void ldsm_x2(uint32_t* r, uint32_t a) {
    asm volatile("ldmatrix.sync.aligned.m8n8.x2.shared.b16 {%0,%1}, [%2];"
        : "=r"(r[0]), "=r"(r[1]) : "r"(a));
}
__device__ __forceinline__ void mma_bf16(float* c, const uint32_t* a, const uint32_t* b) {
    asm volatile("mma.sync.aligned.m16n8k16.row.col.f32.bf16.bf16.f32 "
        "{%0,%1,%2,%3}, {%4,%5,%6,%7}, {%8,%9}, {%0,%1,%2,%3};"
        : "+f"(c[0]), "+f"(c[1]), "+f"(c[2]), "+f"(c[3])
        : "r"(a[0]), "r"(a[1]), "r"(a[2]), "r"(a[3]), "r"(b[0]), "r"(b[1]));
}
__device__ __forceinline__ void cp_async16(uint32_t dst, const void* src) {
    asm volatile("cp.async.cg.shared.global [%0], [%1], 16;"
        :: "r"(dst), "l"(src) : "memory");
}
__device__ __forceinline__ void cp_commit() {
    asm volatile("cp.async.commit_group;" ::: "memory");
}
__device__ __forceinline__ void split_bf16(float v, __nv_bfloat16& h, __nv_bfloat16& l) {
    h = __float2bfloat16(v);
    l = __float2bfloat16(v - __bfloat162float(h));
}

// GEMM tiling
#define KC       32                 // k per chunk (bf16)
#define ROWBF    40                 // row stride in bf16 (80B, conflict-free)
#define TILE_B   (128 * ROWBF * 2)  // 10240 bytes per operand tile
#define STAGE_B  (4 * TILE_B)       // 40960 bytes (Ah, Al, Bh, Bl)
#define GSMEM    (2 * STAGE_B)      // 81920 double-buffered

// ---------------------------------------------------------------------------
// Split-bf16 tensor-core GEMM: C[M,N](fp32) = A[M,K] @ B^T.
// A = Ah+Al [M][K] bf16 row-major; B = Bh+Bl [N][K] bf16 (K-major).
// 128x128 tile/CTA, 8 warps (2x4), warp tile 64x32, cp.async double buffer.
// ---------------------------------------------------------------------------
__device__ __forceinline__ void gemm_load_chunk(
    char* stg, const __nv_bfloat16* Ah, const __nv_bfloat16* Al,
    const __nv_bfloat16* Bh, const __nv_bfloat16* Bl,
    int bm, int bn, int K, int k0, int tid)
{
    const __nv_bfloat16* bases[4] = {Ah, Al, Bh, Bl};
    #pragma unroll
    for (int j = 0; j < 8; j++) {
        const int tile = j >> 1;               // compile-time per j
        const int e = ((j & 1) << 8) + tid;    // 0..511
        const int row = e >> 2;
        const int c = e & 3;                   // 16B chunk (8 bf16)
        const int gr = (tile < 2 ? bm : bn) + row;
        const __nv_bfloat16* src = bases[tile] + (size_t)gr * K + k0 + (c << 3);
        uint32_t dst = sptr(stg + tile * TILE_B + row * (ROWBF * 2) + (c << 4));
        cp_async16(dst, src);
    }
    cp_commit();
}

__global__ void __launch_bounds__(256, 2) gemm_mma_kernel(
    const __nv_bfloat16* __restrict__ Ah, const __nv_bfloat16* __restrict__ Al,
    const __nv_bfloat16* __restrict__ Bh, const __nv_bfloat16* __restrict__ Bl,
    float* __restrict__ C, int M, int N, int K)
{
    extern __shared__ __align__(16) char smem[];
    const int tid  = threadIdx.x;
    const int lane = tid & 31;
    const int warp = tid >> 5;
    const int wm = warp >> 2;           // 0..1
    const int wn = warp & 3;            // 0..3
    const int bm = blockIdx.y * 128;
    const int bn = blockIdx.x * 128;

    float c[4][4][4];
    #pragma unroll
    for (int mt = 0; mt < 4; mt++)
        #pragma unroll
        for (int nt = 0; nt < 4; nt++)
            #pragma unroll
            for (int i = 0; i < 4; i++) c[mt][nt][i] = 0.f;

    const int NC = K / KC;
    gemm_load_chunk(smem, Ah, Al, Bh, Bl, bm, bn, K, 0, tid);

    for (int i = 0; i < NC; i++) {
        if (i + 1 < NC) {
            gemm_load_chunk(smem + ((i + 1) & 1) * STAGE_B,
                            Ah, Al, Bh, Bl, bm, bn, K, (i + 1) * KC, tid);
            asm volatile("cp.async.wait_group 1;" ::: "memory");
        } else {
            asm volatile("cp.async.wait_group 0;" ::: "memory");
        }
        __syncthreads();

        char* stg = smem + (i & 1) * STAGE_B;
        __nv_bfloat16 (*sAh)[ROWBF] = (__nv_bfloat16(*)[ROWBF])(stg);
        __nv_bfloat16 (*sAl)[ROWBF] = (__nv_bfloat16(*)[ROWBF])(stg + TILE_B);
        __nv_bfloat16 (*sBh)[ROWBF] = (__nv_bfloat16(*)[ROWBF])(stg + 2 * TILE_B);
        __nv_bfloat16 (*sBl)[ROWBF] = (__nv_bfloat16(*)[ROWBF])(stg + 3 * TILE_B);

        #pragma unroll
        for (int s = 0; s < 2; s++) {          // two k16 steps per chunk
            uint32_t bh[4][2], bl[4][2];
            const int b_r = lane & 7;
            const int b_c = s * 16 + (((lane >> 3) & 1) << 3);
            #pragma unroll
            for (int nt = 0; nt < 4; nt++) {
                ldsm_x2(bh[nt], sptr(&sBh[wn * 32 + nt * 8 + b_r][b_c]));
                ldsm_x2(bl[nt], sptr(&sBl[wn * 32 + nt * 8 + b_r][b_c]));
            }
            const int a_r = (lane & 7) | (((lane >> 3) & 1) << 3);
            const int a_c = s * 16 + (((lane >> 4) & 1) << 3);
            #pragma unroll
            for (int mt = 0; mt < 4; mt++) {
                uint32_t ah[4], al[4];
                ldsm_x4(ah, sptr(&sAh[wm * 64 + mt * 16 + a_r][a_c]));
                ldsm_x4(al, sptr(&sAl[wm * 64 + mt * 16 + a_r][a_c]));
                #pragma unroll
                for (int nt = 0; nt < 4; nt++) {
                    mma_bf16(c[mt][nt], ah, bh[nt]);   // hi*hi
                    mma_bf16(c[mt][nt], ah, bl[nt]);   // hi*lo
                    mma_bf16(c[mt][nt], al, bh[nt]);   // lo*hi
                }
            }
        }
        __syncthreads();
    }

    // ---- epilogue (fragment layout verified in R4) ----
    #pragma unroll
    for (int mt = 0; mt < 4; mt++) {
        int row = bm + wm * 64 + mt * 16 + (lane >> 2);
        #pragma unroll
        for (int nt = 0; nt < 4; nt++) {
            int col = bn + wn * 32 + nt * 8 + ((lane & 3) << 1);
            *(float2*)(C + (size_t)row * N + col)       = make_float2(c[mt][nt][0], c[mt][nt][1]);
            *(float2*)(C + (size_t)(row + 8) * N + col) = make_float2(c[mt][nt][2], c[mt][nt][3]);
        }
    }
}

// ---------------------------------------------------------------------------
// fp32 -> hi/lo bf16 split (no transpose): 4 elements per thread
// ---------------------------------------------------------------------------
__global__ void split_kernel(const float* __restrict__ in,
                             __nv_bfloat16* __restrict__ oh,
                             __nv_bfloat16* __restrict__ ol, int n)
{
    int i = (blockIdx.x * blockDim.x + threadIdx.x) << 2;
    if (i >= n) return;
    float4 v = *(const float4*)(in + i);
    float vv[4] = {v.x, v.y, v.z, v.w};
    __nv_bfloat16 h[4], l[4];
    #pragma unroll
    for (int j = 0; j < 4; j++) split_bf16(vv[j], h[j], l[j]);
    *(uint2*)(oh + i) = *(uint2*)h;
    *(uint2*)(ol + i) = *(uint2*)l;
}

// ---------------------------------------------------------------------------
// weight transpose + split: in [K][N] fp32 -> out [N][K] hi/lo bf16
// ---------------------------------------------------------------------------
__global__ void transpose_split_kernel(const float* __restrict__ W,
                                       __nv_bfloat16* __restrict__ oh,
                                       __nv_bfloat16* __restrict__ ol,
                                       int K, int N)
{
    __shared__ float t[32][33];
    const int k0 = blockIdx.y << 5, n0 = blockIdx.x << 5;
    const int c = threadIdx.x & 31, r = threadIdx.x >> 5;
    #pragma unroll
    for (int it = 0; it < 4; it++) {
        int row = r + (it << 3);
        t[row][c] = W[(size_t)(k0 + row) * N + n0 + c];
    }
    __syncthreads();
    #pragma unroll
    for (int it = 0; it < 4; it++) {
        int n = r + (it << 3);
        float v = t[c][n];
        __nv_bfloat16 h, l;
        split_bf16(v, h, l);
        oh[(size_t)(n0 + n) * K + k0 + c] = h;
        ol[(size_t)(n0 + n) * K + k0 + c] = l;
    }
}

// ---------------------------------------------------------------------------
// RoPE in-place on g_q (8 heads) and g_k (4 heads).
// ---------------------------------------------------------------------------
__global__ void rope_kernel(const int* __restrict__ pos_ids)
{
    int idx = blockIdx.x * blockDim.x + threadIdx.x;
    if (idx >= MTOK * 12 * 128) return;
    int d  = idx & 127;
    int r  = idx >> 7;
    int hh = r % 12;
    int t  = r / 12;
    float pos = (float)pos_ids[t];
    float inv = __expf((float)d * -0.07195578415606394f);
    float ang = pos * inv;
    float sn, cs;
    sincosf(ang, &sn, &cs);
    float* base = (hh < 8) ? (g_q + (size_t)t * QCOLS + hh * HD)
                           : (g_k + (size_t)t * KCOLS + (hh - 8) * HD);
    float x1 = base[d];
    float x2 = base[d + 128];
    base[d]       = x1 * cs - x2 * sn;
    base[d + 128] = x2 * cs + x1 * sn;
}

// ---------------------------------------------------------------------------
// Sliding-window causal flash attention with tanh softcap (f32x2, unchanged).
// ---------------------------------------------------------------------------
__global__ void __launch_bounds__(256, 2) attn_kernel()
{
    __shared__ __align__(16) float sQ[16][68];
    __shared__ __align__(16) float sK[16][68];
    __shared__ __align__(16) float sP[64][69];
    __shared__ __align__(16) float sV[16][264];

    const int qt = blockIdx.x, h = blockIdx.y, b = blockIdx.z;
    const int kvh = h >> 1;
    const int q0 = qt * 64;
    const int tid = threadIdx.x;
    const int tx = tid & 15, ty = tid >> 4;

    const float* Qg = g_q + ((size_t)(b * SLEN + q0)) * QCOLS + h * HD;
    const float* Kg = g_k + ((size_t)(b * SLEN)) * KCOLS + kvh * HD;
    const float* Vg = g_v + ((size_t)(b * SLEN)) * KCOLS + kvh * HD;

    ull acc[4][8];
    #pragma unroll
    for (int i = 0; i < 4; i++)
        #pragma unroll
        for (int j = 0; j < 8; j++) acc[i][j] = 0ull;
    float mrow[4] = {-1e30f, -1e30f, -1e30f, -1e30f};
    float lrow[4] = {0.f, 0.f, 0.f, 0.f};

    const int ld_d = tid & 15;
    const int ld_q = tid >> 4;

    const int kb_start = (qt >= 8) ? (qt - 8) : 0;
    for (int kb = kb_start; kb <= qt; kb++) {
        ull s[4][2];
        #pragma unroll
        for (int i = 0; i < 4; i++) { s[i][0] = 0ull; s[i][1] = 0ull; }

        for (int dc = 0; dc < HD; dc += 16) {
            __syncthreads();
            #pragma unroll
            for (int r = 0; r < 4; r++) {
                int row = ld_q + 16 * r;
                sQ[ld_d][row] = Qg[(size_t)row * QCOLS + dc + ld_d];
                sK[ld_d][row] = Kg[(size_t)(kb * 64 + row) * KCOLS + dc + ld_d];
            }
            __syncthreads();
            #pragma unroll
            for (int d = 0; d < 16; d++) {
                const ull* kp = (const ull*)&sK[d][tx << 2];
                ull b0 = kp[0], b1 = kp[1];
                #pragma unroll
                for (int i = 0; i < 4; i++) {
                    ull ad = pack_dup(sQ[d][(ty << 2) + i]);
                    fma2(s[i][0], ad, b0);
                    fma2(s[i][1], ad, b1);
                }
            }
        }

        float sc[4][4];
        const int ig0 = q0 + (ty << 2);
        const int jg0 = kb * 64 + (tx << 2);
        #pragma unroll
        for (int i = 0; i < 4; i++) {
            float v0, v1, v2, v3;
            unpack2(s[i][0], v0, v1);
            unpack2(s[i][1], v2, v3);
            float vv[4] = {v0, v1, v2, v3};
            int ig = ig0 + i;
            #pragma unroll
            for (int j = 0; j < 4; j++) {
                int jg = jg0 + j;
                float x = vv[j] * 0.0625f;
                float t = __expf(x * 0.04f);
                float cc = 50.f * (t - 1.f) / (t + 1.f);
                bool valid = (jg <= ig) && (ig - jg < WIN);
                sc[i][j] = valid ? cc : -1e30f;
            }
        }
        #pragma unroll
        for (int i = 0; i < 4; i++) {
            float rmax = fmaxf(fmaxf(sc[i][0], sc[i][1]), fmaxf(sc[i][2], sc[i][3]));
            #pragma unroll
            for (int mseg = 1; mseg < 16; mseg <<= 1)
                rmax = fmaxf(rmax, __shfl_xor_sync(0xffffffffu, rmax, mseg));
            float mnew = fmaxf(mrow[i], rmax);
            float alpha = __expf(mrow[i] - mnew);
            float rsum = 0.f;
            #pragma unroll
            for (int j = 0; j < 4; j++) {
                float p = (sc[i][j] < -1e29f) ? 0.f : __expf(sc[i][j] - mnew);
                sc[i][j] = p;
                rsum += p;
            }
            #pragma unroll
            for (int mseg = 1; mseg < 16; mseg <<= 1)
                rsum += __shfl_xor_sync(0xffffffffu, rsum, mseg);
            lrow[i] = lrow[i] * alpha + rsum;
            mrow[i] = mnew;
            ull ad = pack_dup(alpha);
            #pragma unroll
            for (int j2 = 0; j2 < 8; j2++) mul2(acc[i][j2], ad);
        }
        #pragma unroll
        for (int i = 0; i < 4; i++)
            #pragma unroll
            for (int j = 0; j < 4; j++)
                sP[(tx << 2) + j][(ty << 2) + i] = sc[i][j];

        const int vkk = tid >> 6;
        const int vc4 = (tid & 63) << 2;
        for (int kc = 0; kc < 4; kc++) {
            __syncthreads();
            const float* vb = Vg + (size_t)(kb * 64 + kc * 16) * KCOLS;
            #pragma unroll
            for (int r = 0; r < 4; r++) {
                float4 vv = *(const float4*)(vb + (size_t)(vkk + 4 * r) * KCOLS + vc4);
                *(float4*)&sV[vkk + 4 * r][vc4] = vv;
            }
            __syncthreads();
            #pragma unroll
            for (int k = 0; k < 16; k++) {
                ull vreg[8];
                #pragma unroll
                for (int j = 0; j < 4; j++) {
                    const ull* vp = (const ull*)&sV[k][(j << 6) + (tx << 2)];
                    vreg[2 * j] = vp[0];
                    vreg[2 * j + 1] = vp[1];
                }
                #pragma unroll
                for (int i = 0; i < 4; i++) {
                    ull pd = pack_dup(sP[kc * 16 + k][(ty << 2) + i]);
                    #pragma unroll
                    for (int j2 = 0; j2 < 8; j2++) fma2(acc[i][j2], pd, vreg[j2]);
                }
            }
        }
    }

    const int t0 = b * SLEN + q0;
    #pragma unroll
    for (int i = 0; i < 4; i++) {
        float rl = 1.f / lrow[i];
        float* ob = g_attn + (size_t)(t0 + (ty << 2) + i) * QCOLS + h * HD;
        #pragma unroll
        for (int j = 0; j < 4; j++) {
            float o0, o1, o2, o3;
            unpack2(acc[i][2 * j],     o0, o1);
            unpack2(acc[i][2 * j + 1], o2, o3);
            *(float4*)(ob + (j << 6) + (tx << 2)) =
                make_float4(o0 * rl, o1 * rl, o2 * rl, o3 * rl);
        }
    }
}

// ---------------------------------------------------------------------------
extern "C" void kernel_launch(void* const* d_in, const int* in_sizes, int n_in,
                              void* d_out, int out_size) {
    const float* hidden = (const float*)d_in[0];
    const int*   pos    = (const int*)d_in[2];
    const float* Wq     = (const float*)d_in[3];
    const float* Wk     = (const float*)d_in[4];
    const float* Wv     = (const float*)d_in[5];
    const float* Wo     = (const float*)d_in[6];
    float* out = (float*)d_out;

    cudaFuncSetAttribute(gemm_mma_kernel,
        cudaFuncAttributeMaxDynamicSharedMemorySize, GSMEM);

    void *hidH, *hidL, *wqH, *wqL, *wkH, *wkL, *wvH, *wvL, *woH, *woL, *aoH, *aoL, *attnp;
    cudaGetSymbolAddress(&hidH, g_hidH); cudaGetSymbolAddress(&hidL, g_hidL);
    cudaGetSymbolAddress(&wqH, g_wqH);   cudaGetSymbolAddress(&wqL, g_wqL);
    cudaGetSymbolAddress(&wkH, g_wkH);   cudaGetSymbolAddress(&wkL, g_wkL);
    cudaGetSymbolAddress(&wvH, g_wvH);   cudaGetSymbolAddress(&wvL, g_wvL);
    cudaGetSymbolAddress(&woH, g_woH);   cudaGetSymbolAddress(&woL, g_woL);
    cudaGetSymbolAddress(&aoH, g_aoH);   cudaGetSymbolAddress(&aoL, g_aoL);
    cudaGetSymbolAddress(&attnp, g_attn);
    void *gq, *gk, *gv;
    cudaGetSymbolAddress(&gq, g_q); cudaGetSymbolAddress(&gk, g_k);
    cudaGetSymbolAddress(&gv, g_v);

    dim3 thr(256);

    // ---- one-time operand conversion ----
    split_kernel<<<(MTOK * HDIM / 4 + 255) / 256, thr>>>(
        hidden, (__nv_bfloat16*)hidH, (__nv_bfloat16*)hidL, MTOK * HDIM);
    transpose_split_kernel<<<dim3(QCOLS / 32, HDIM / 32), thr>>>(
        Wq, (__nv_bfloat16*)wqH, (__nv_bfloat16*)wqL, HDIM, QCOLS);
    transpose_split_kernel<<<dim3(KCOLS / 32, HDIM / 32), thr>>>(
        Wk, (__nv_bfloat16*)wkH, (__nv_bfloat16*)wkL, HDIM, KCOLS);
    transpose_split_kernel<<<dim3(KCOLS / 32, HDIM / 32), thr>>>(
        Wv, (__nv_bfloat16*)wvH, (__nv_bfloat16*)wvL, HDIM, KCOLS);
    transpose_split_kernel<<<dim3(HDIM / 32, QCOLS / 32), thr>>>(
        Wo, (__nv_bfloat16*)woH, (__nv_bfloat16*)woL, QCOLS, HDIM);

    // ---- QKV projections (mma.sync, pre-split bf16 feed) ----
    gemm_mma_kernel<<<dim3(QCOLS / 128, MTOK / 128), thr, GSMEM>>>(
        (__nv_bfloat16*)hidH, (__nv_bfloat16*)hidL,
        (__nv_bfloat16*)wqH, (__nv_bfloat16*)wqL,
        (float*)gq, MTOK, QCOLS, HDIM);
    gemm_mma_kernel<<<dim3(KCOLS / 128, MTOK / 128), thr, GSMEM>>>(
        (__nv_bfloat16*)hidH, (__nv_bfloat16*)hidL,
        (__nv_bfloat16*)wkH, (__nv_bfloat16*)wkL,
        (float*)gk, MTOK, KCOLS, HDIM);
    gemm_mma_kernel<<<dim3(KCOLS / 128, MTOK / 128), thr, GSMEM>>>(
        (__nv_bfloat16*)hidH, (__nv_bfloat16*)hidL,
        (__nv_bfloat16*)wvH, (__nv_bfloat16*)wvL,
        (float*)gv, MTOK, KCOLS, HDIM);

    // ---- RoPE ----
    int rope_threads = MTOK * 12 * 128;
    rope_kernel<<<(rope_threads + 255) / 256, thr>>>(pos);

    // ---- attention ----
    attn_kernel<<<dim3(SLEN / 64, NHQ, BTCH), thr>>>();

    // ---- attention output split + O projection ----
    split_kernel<<<(MTOK * QCOLS / 4 + 255) / 256, thr>>>(
        (const float*)attnp, (__nv_bfloat16*)aoH, (__nv_bfloat16*)aoL, MTOK * QCOLS);
    gemm_mma_kernel<<<dim3(HDIM / 128, MTOK / 128), thr, GSMEM>>>(
        (__nv_bfloat16*)aoH, (__nv_bfloat16*)aoL,
        (__nv_bfloat16*)woH, (__nv_bfloat16*)woL,
        out, MTOK, HDIM, QCOLS);
}